// round 2
// baseline (speedup 1.0000x reference)
#include <cuda_runtime.h>
#include <math.h>

// Grid is 256^3 voxels, 1 byte per voxel (thermometer-coded level, 7 bits used).
// Level L = 7 - d2 (d2 in 0..6), byte code = (1<<L)-1. OR of codes == code of max level.
#define GDIM   256
#define WORDS  (GDIM*GDIM*GDIM/4)   // 4,194,304 u32 words per grid
#define VQUADS (WORDS/4)            // 1,048,576 uint4 per grid
#define RBLOCKS 1024
#define RTHREADS 256

__device__ uint4 g_src[VQUADS];     // zero-initialized at module load; re-zeroed by reduce
__device__ uint4 g_tgt[VQUADS];
__device__ float g_part[RBLOCKS];

// 5-byte row patterns (dx = -2..2 in bytes 0..4) indexed by s2 = d0^2 + d1^2.
// byte = thermo(s2 + dx^2), thermo(d2) = (1 << (7-d2)) - 1 for d2<=6 else 0.
__device__ __constant__ unsigned long long c_PAT[9] = {
    0x00000007'3F7F3F07ULL,  // s2=0 : d2 = 4,1,0,1,4
    0x00000003'1F3F1F03ULL,  // s2=1 : d2 = 5,2,1,2,5
    0x00000001'0F1F0F01ULL,  // s2=2 : d2 = 6,3,2,3,6
    0ULL,                    // s2=3 (does not occur)
    0x00000000'03070300ULL,  // s2=4 : d2 = 8,5,4,5,8
    0x00000000'01030100ULL,  // s2=5 : d2 = 9,6,5,6,9
    0ULL, 0ULL, 0ULL         // s2=6,7 don't occur; s2=8 all out of band
};

__global__ void splat_kernel(const float* __restrict__ src,
                             const float* __restrict__ tgt,
                             const float* __restrict__ ox,
                             const float* __restrict__ oy,
                             const float* __restrict__ oz,
                             const float* __restrict__ vx,
                             int N)
{
    int t = blockIdx.x * blockDim.x + threadIdx.x;
    if (t >= 2 * N) return;
    bool isSrc = (t < N);
    const float* c = isSrc ? src : tgt;
    unsigned int* grid = (unsigned int*)(isSrc ? g_src : g_tgt);
    int n = isSrc ? t : (t - N);

    float v = vx[0];
    // IEEE divide regardless of fast-math so floor() matches the reference exactly.
    float fx = __fdiv_rn(c[n]         - ox[0], v);
    float fy = __fdiv_rn(c[N + n]     - oy[0], v);
    float fz = __fdiv_rn(c[2 * N + n] - oz[0], v);
    int i0 = (int)floorf(fx);
    int i1 = (int)floorf(fy);
    int i2 = (int)floorf(fz);
    // center_ok: atom's own voxel inside the grid
    if ((unsigned)i0 > 255u || (unsigned)i1 > 255u || (unsigned)i2 > 255u) return;

    int start0 = i2 - 2;

#pragma unroll
    for (int d0 = -2; d0 <= 2; d0++) {
#pragma unroll
        for (int d1 = -2; d1 <= 2; d1++) {
            const int s2 = d0 * d0 + d1 * d1;
            if (s2 >= 8) continue;           // 4 corners: whole row out of band
            int j0 = i0 + d0;
            int j1 = i1 + d1;
            if ((unsigned)j0 > 255u || (unsigned)j1 > 255u) continue;
            unsigned long long p = c_PAT[s2];
            int start = start0;
            if (start < 0) { p >>= (unsigned)(-start) * 8u; start = 0; }
            int avail = 256 - start;
            if (avail < 5) p &= (1ULL << (avail * 8)) - 1ULL;
            unsigned long long sv = p << ((start & 3) * 8);
            unsigned w = ((unsigned)(j0 * 256 + j1)) * 64u + (unsigned)(start >> 2);
            unsigned lo = (unsigned)sv;
            unsigned hi = (unsigned)(sv >> 32);
            if (lo) atomicOr(&grid[w], lo);
            if (hi) atomicOr(&grid[w + 1], hi);
        }
    }
}

__global__ void reduce_kernel()
{
    __shared__ float stab[8];
    __shared__ float wsum[8];
    if (threadIdx.x < 8) {
        const float KK = (float)((3.14159265358979323846 / 3.5) * (3.14159265358979323846 / 3.5));
        // stab[L] = exp(-K * (7-L)); L = popc(thermometer byte); stab[0] = 0 (empty voxel)
        stab[threadIdx.x] = (threadIdx.x == 0) ? 0.0f
                                               : expf(-KK * (float)(7 - (int)threadIdx.x));
    }
    __syncthreads();

    float acc = 0.0f;
    const uint4 z4 = make_uint4(0u, 0u, 0u, 0u);
    const int stride = gridDim.x * blockDim.x;
    for (int i = blockIdx.x * blockDim.x + threadIdx.x; i < VQUADS; i += stride) {
        uint4 s = g_src[i];
        uint4 t = g_tgt[i];
        unsigned sAny = s.x | s.y | s.z | s.w;
        unsigned tAny = t.x | t.y | t.z | t.w;
        if (sAny) {
            const unsigned sw[4] = { s.x, s.y, s.z, s.w };
            const unsigned tw[4] = { t.x, t.y, t.z, t.w };
#pragma unroll
            for (int l = 0; l < 4; l++) {
                unsigned a = sw[l], b = tw[l];
                if (a == 0u) continue;       // src=0 everywhere -> contribution 0
#pragma unroll
                for (int k = 0; k < 4; k++) {
                    float fs = stab[__popc((a >> (k * 8)) & 255u)];
                    float ft = stab[__popc((b >> (k * 8)) & 255u)];
                    acc += fs * (fs - ft);
                }
            }
            g_src[i] = z4;                   // reset for next graph replay
        }
        if (tAny) g_tgt[i] = z4;
    }

    // deterministic block reduction
#pragma unroll
    for (int off = 16; off > 0; off >>= 1)
        acc += __shfl_down_sync(0xFFFFFFFFu, acc, off);
    int warp = threadIdx.x >> 5;
    if ((threadIdx.x & 31) == 0) wsum[warp] = acc;
    __syncthreads();
    if (threadIdx.x == 0) {
        float b = 0.0f;
#pragma unroll
        for (int wdx = 0; wdx < RTHREADS / 32; wdx++) b += wsum[wdx];
        g_part[blockIdx.x] = b;
    }
}

__global__ void finish_kernel(float* __restrict__ out)
{
    __shared__ double wsum[8];
    double a = 0.0;
    for (int i = threadIdx.x; i < RBLOCKS; i += blockDim.x)
        a += (double)g_part[i];
#pragma unroll
    for (int off = 16; off > 0; off >>= 1)
        a += __shfl_down_sync(0xFFFFFFFFu, a, off);
    int warp = threadIdx.x >> 5;
    if ((threadIdx.x & 31) == 0) wsum[warp] = a;
    __syncthreads();
    if (threadIdx.x == 0) {
        double tot = 0.0;
#pragma unroll
        for (int wdx = 0; wdx < 8; wdx++) tot += wsum[wdx];
        out[0] = (float)tot;
    }
}

extern "C" void kernel_launch(void* const* d_in, const int* in_sizes, int n_in,
                              void* d_out, int out_size)
{
    const float* src = (const float*)d_in[0];
    const float* tgt = (const float*)d_in[1];
    const float* ox  = (const float*)d_in[2];
    const float* oy  = (const float*)d_in[3];
    const float* oz  = (const float*)d_in[4];
    const float* vx  = (const float*)d_in[5];
    int N = in_sizes[0] / 3;

    int total = 2 * N;
    int blocks = (total + 255) / 256;
    splat_kernel<<<blocks, 256>>>(src, tgt, ox, oy, oz, vx, N);
    reduce_kernel<<<RBLOCKS, RTHREADS>>>();
    finish_kernel<<<1, 256>>>((float*)d_out);
}

// round 3
// speedup vs baseline: 1.9106x; 1.9106x over previous
#include <cuda_runtime.h>
#include <math.h>

// 256^3 grid, 1 byte/voxel thermometer code: level L = 7 - d2 (d2 in 0..6),
// byte = (1<<L)-1. atomicOr of thermometer codes == thermometer of max level.
#define GDIM    256
#define WORDS   (GDIM*GDIM*GDIM/4)   // 4,194,304 u32 words per grid
#define VQUADS  (WORDS/4)            // 1,048,576 uint4 per grid
#define RBLOCKS 1024
#define RTHREADS 256
#define QPT     4                    // quads per thread: VQUADS / (RBLOCKS*RTHREADS)

__device__ uint4 g_src[VQUADS];      // zero at load; re-zeroed by reduce each call
__device__ uint4 g_tgt[VQUADS];
__device__ float g_part[RBLOCKS];
__device__ unsigned int g_count;

// 5-byte row patterns (dz = -2..2 in bytes 0..4), indexed by s2 = d0^2 + d1^2.
// byte = thermo(s2 + dz^2); thermo(d2) = (1 << (7-d2)) - 1 for d2<=6 else 0.
__device__ __constant__ unsigned long long c_PAT[8] = {
    0x00000007'3F7F3F07ULL,  // s2=0
    0x00000003'1F3F1F03ULL,  // s2=1
    0x00000001'0F1F0F01ULL,  // s2=2
    0ULL,                    // s2=3 (unused)
    0x00000000'03070300ULL,  // s2=4
    0x00000000'01030100ULL,  // s2=5
    0ULL, 0ULL
};

// One thread per (atom, d0 slice): 2N*5 threads total.
__global__ void splat_kernel(const float* __restrict__ src,
                             const float* __restrict__ tgt,
                             const float* __restrict__ ox,
                             const float* __restrict__ oy,
                             const float* __restrict__ oz,
                             const float* __restrict__ vx,
                             int N)
{
    __shared__ unsigned long long spat[8];
    if (threadIdx.x < 8) spat[threadIdx.x] = c_PAT[threadIdx.x];
    __syncthreads();

    int t = blockIdx.x * blockDim.x + threadIdx.x;
    if (t >= 2 * N * 5) return;
    int a  = t / 5;
    int d0 = t - a * 5 - 2;
    bool isSrc = (a < N);
    const float* c = isSrc ? src : tgt;
    unsigned long long* grid = (unsigned long long*)(isSrc ? g_src : g_tgt);
    int n = isSrc ? a : (a - N);

    float v = vx[0];
    // IEEE f32 divide so floor matches the reference bit-exactly.
    float fx = __fdiv_rn(c[n]         - ox[0], v);
    float fy = __fdiv_rn(c[N + n]     - oy[0], v);
    float fz = __fdiv_rn(c[2 * N + n] - oz[0], v);
    int i0 = (int)floorf(fx);
    int i1 = (int)floorf(fy);
    int i2 = (int)floorf(fz);
    if ((unsigned)i0 > 255u || (unsigned)i1 > 255u || (unsigned)i2 > 255u) return;

    int j0 = i0 + d0;
    if ((unsigned)j0 > 255u) return;
    int d02 = d0 * d0;

    // z-clip amounts are shared across all rows of this thread
    int start = i2 - 2;
    unsigned rsh = 0;
    if (start < 0) { rsh = (unsigned)(-start) * 8u; start = 0; }
    unsigned long long msk = ~0ULL;
    int avail = 256 - start;
    if (avail < 5) msk = (1ULL << (avail * 8)) - 1ULL;   // avail >= 3 always
    unsigned shl   = (unsigned)(start & 7) * 8u;
    unsigned qoff  = (unsigned)(start >> 3);
    unsigned rbase = ((unsigned)(j0 * 256 + i1)) * 32u + qoff;

#pragma unroll
    for (int d1 = -2; d1 <= 2; d1++) {
        int s2 = d02 + d1 * d1;
        if (s2 >= 8) continue;                  // only trims d1=+-2 when d02==4
        int j1 = i1 + d1;
        if ((unsigned)j1 > 255u) continue;
        unsigned long long p = (spat[s2] >> rsh) & msk;
        __uint128_t sv = (__uint128_t)p << shl;
        unsigned long long lo = (unsigned long long)sv;
        unsigned long long hi = (unsigned long long)(sv >> 64);
        unsigned q = rbase + (unsigned)d1 * 32u;
        if (lo) atomicOr(&grid[q], lo);
        if (hi) atomicOr(&grid[q + 1], hi);
    }
}

// Reduce + zero + final sum in one kernel (last-block-done pattern).
// src^2 term decoded two voxels at a time: for a halfword of thermometer bytes,
// key = b0 + b1 = 2^L1 + 2^L2 - 2 is a perfect hash of the unordered (L1,L2)
// pair, and g(L1)+g(L2) is symmetric -> single shared-mem LUT hit per halfword.
__global__ void reduce_kernel(float* __restrict__ out)
{
    __shared__ float s2tab[256];
    __shared__ float ctab[16];
    __shared__ float wsum[RTHREADS / 32];
    __shared__ double wsumd[RTHREADS / 32];
    __shared__ bool  isLast;

    const float KK = (float)((3.14159265358979323846 / 3.5) * (3.14159265358979323846 / 3.5));

    for (int i = threadIdx.x; i < 256; i += blockDim.x) s2tab[i] = 0.0f;
    if (threadIdx.x < 16) ctab[threadIdx.x] = 0.0f;
    __syncthreads();
    if (threadIdx.x < 64) {
        int L1 = threadIdx.x >> 3, L2 = threadIdx.x & 7;
        float g1 = L1 ? expf(-2.0f * KK * (float)(7 - L1)) : 0.0f;
        float g2 = L2 ? expf(-2.0f * KK * (float)(7 - L2)) : 0.0f;
        s2tab[(1 << L1) + (1 << L2) - 2] = g1 + g2;   // symmetric; dup writes benign
    }
    if (threadIdx.x < 13) {
        int m = (int)threadIdx.x + 2;                 // m = Ls + Lt in [2,14]
        ctab[m] = expf(-KK * (float)(14 - m));
    }
    __syncthreads();

    float acc = 0.0f;
    const uint4 z4 = make_uint4(0u, 0u, 0u, 0u);
    int base = (blockIdx.x * blockDim.x + threadIdx.x) * QPT;

    uint4 s[QPT], tq[QPT];
#pragma unroll
    for (int k = 0; k < QPT; k++) s[k]  = g_src[base + k];
#pragma unroll
    for (int k = 0; k < QPT; k++) tq[k] = g_tgt[base + k];

#pragma unroll
    for (int k = 0; k < QPT; k++) {
        unsigned sw[4] = { s[k].x,  s[k].y,  s[k].z,  s[k].w  };
        unsigned tw[4] = { tq[k].x, tq[k].y, tq[k].z, tq[k].w };
        unsigned sAny = sw[0] | sw[1] | sw[2] | sw[3];
        unsigned tAny = tw[0] | tw[1] | tw[2] | tw[3];
        if (sAny) {
            float a0 = 0.0f, a1 = 0.0f;
#pragma unroll
            for (int l = 0; l < 4; l++) {
                unsigned w = sw[l];
                a0 += s2tab[__dp4a(w, 0x00000101u, 0u)];   // bytes 0+1
                a1 += s2tab[__dp4a(w, 0x01010000u, 0u)];   // bytes 2+3
                unsigned u = w & tw[l];                     // both-occupied voxels
                if (u) {
#pragma unroll
                    for (int b = 0; b < 4; b++) {
                        if ((u >> (b * 8)) & 255u) {
                            int m = __popc((w >> (b * 8)) & 255u)
                                  + __popc((tw[l] >> (b * 8)) & 255u);
                            acc -= ctab[m];
                        }
                    }
                }
            }
            acc += a0 + a1;
            g_src[base + k] = z4;       // reset for next graph replay
        }
        if (tAny) g_tgt[base + k] = z4;
    }

    // deterministic block reduction
#pragma unroll
    for (int off = 16; off > 0; off >>= 1)
        acc += __shfl_down_sync(0xFFFFFFFFu, acc, off);
    int warp = threadIdx.x >> 5;
    if ((threadIdx.x & 31) == 0) wsum[warp] = acc;
    __syncthreads();
    if (threadIdx.x == 0) {
        float b = 0.0f;
#pragma unroll
        for (int wdx = 0; wdx < RTHREADS / 32; wdx++) b += wsum[wdx];
        g_part[blockIdx.x] = b;
        __threadfence();
        unsigned vdone = atomicAdd(&g_count, 1u);
        isLast = (vdone == (unsigned)gridDim.x - 1u);
        if (isLast) g_count = 0u;     // reset for next replay
    }
    __syncthreads();

    if (isLast) {
        double a = 0.0;
        for (int i = threadIdx.x; i < RBLOCKS; i += blockDim.x)
            a += (double)g_part[i];
#pragma unroll
        for (int off = 16; off > 0; off >>= 1)
            a += __shfl_down_sync(0xFFFFFFFFu, a, off);
        if ((threadIdx.x & 31) == 0) wsumd[warp] = a;
        __syncthreads();
        if (threadIdx.x == 0) {
            double tot = 0.0;
#pragma unroll
            for (int wdx = 0; wdx < RTHREADS / 32; wdx++) tot += wsumd[wdx];
            out[0] = (float)tot;
        }
    }
}

extern "C" void kernel_launch(void* const* d_in, const int* in_sizes, int n_in,
                              void* d_out, int out_size)
{
    const float* src = (const float*)d_in[0];
    const float* tgt = (const float*)d_in[1];
    const float* ox  = (const float*)d_in[2];
    const float* oy  = (const float*)d_in[3];
    const float* oz  = (const float*)d_in[4];
    const float* vx  = (const float*)d_in[5];
    int N = in_sizes[0] / 3;

    int total = 2 * N * 5;
    int blocks = (total + 255) / 256;
    splat_kernel<<<blocks, 256>>>(src, tgt, ox, oy, oz, vx, N);
    reduce_kernel<<<RBLOCKS, RTHREADS>>>((float*)d_out);
}

// round 5
// speedup vs baseline: 2.0741x; 1.0856x over previous
#include <cuda_runtime.h>
#include <math.h>

// 256^3 grid, 1 byte/voxel thermometer code: level L = 7 - d2 (d2 in 0..6),
// byte = (1<<L)-1. atomicOr of thermometer codes == thermometer of max level.
#define GDIM    256
#define WORDS   (GDIM*GDIM*GDIM/4)   // 4,194,304 u32 words per grid
#define VQUADS  (WORDS/4)            // 1,048,576 uint4 per grid
#define RBLOCKS 2048
#define RTHREADS 256
#define QPT     2                    // quads per thread: VQUADS / (RBLOCKS*RTHREADS)

__device__ uint4 g_src[VQUADS];      // zero at load; re-zeroed by reduce each call
__device__ uint4 g_tgt[VQUADS];
__device__ float g_part[RBLOCKS];
__device__ unsigned int g_count;

// 5-byte row patterns (dz = -2..2 in bytes 0..4), indexed by s2 = d0^2 + d1^2.
__device__ __constant__ unsigned long long c_PAT[8] = {
    0x00000007'3F7F3F07ULL,  // s2=0
    0x00000003'1F3F1F03ULL,  // s2=1
    0x00000001'0F1F0F01ULL,  // s2=2
    0ULL,
    0x00000000'03070300ULL,  // s2=4
    0x00000000'01030100ULL,  // s2=5
    0ULL, 0ULL
};

// One thread per (atom, d0 slice): 2N*5 threads total.
__global__ void splat_kernel(const float* __restrict__ src,
                             const float* __restrict__ tgt,
                             const float* __restrict__ ox,
                             const float* __restrict__ oy,
                             const float* __restrict__ oz,
                             const float* __restrict__ vx,
                             int N)
{
    __shared__ unsigned long long spat[8];
    if (threadIdx.x < 8) spat[threadIdx.x] = c_PAT[threadIdx.x];
    __syncthreads();

    int t = blockIdx.x * blockDim.x + threadIdx.x;
    if (t >= 2 * N * 5) return;
    int a  = t / 5;
    int d0 = t - a * 5 - 2;
    bool isSrc = (a < N);
    const float* c = isSrc ? src : tgt;
    unsigned long long* grid = (unsigned long long*)(isSrc ? g_src : g_tgt);
    int n = isSrc ? a : (a - N);

    float v = vx[0];
    // IEEE f32 divide so floor matches the reference bit-exactly.
    float fx = __fdiv_rn(c[n]         - ox[0], v);
    float fy = __fdiv_rn(c[N + n]     - oy[0], v);
    float fz = __fdiv_rn(c[2 * N + n] - oz[0], v);
    int i0 = (int)floorf(fx);
    int i1 = (int)floorf(fy);
    int i2 = (int)floorf(fz);
    if ((unsigned)i0 > 255u || (unsigned)i1 > 255u || (unsigned)i2 > 255u) return;

    int j0 = i0 + d0;
    if ((unsigned)j0 > 255u) return;
    int d02 = d0 * d0;

    // z-clip amounts shared across this thread's rows
    int start = i2 - 2;
    unsigned rsh = 0;
    if (start < 0) { rsh = (unsigned)(-start) * 8u; start = 0; }
    unsigned long long msk = ~0ULL;
    int avail = 256 - start;
    if (avail < 5) msk = (1ULL << (avail * 8)) - 1ULL;
    unsigned shl   = (unsigned)(start & 7) * 8u;
    unsigned qoff  = (unsigned)(start >> 3);
    unsigned rbase = ((unsigned)(j0 * 256 + i1)) * 32u + qoff;

#pragma unroll
    for (int d1 = -2; d1 <= 2; d1++) {
        int s2 = d02 + d1 * d1;
        if (s2 >= 8) continue;
        int j1 = i1 + d1;
        if ((unsigned)j1 > 255u) continue;
        unsigned long long p = (spat[s2] >> rsh) & msk;
        __uint128_t sv = (__uint128_t)p << shl;
        unsigned long long lo = (unsigned long long)sv;
        unsigned long long hi = (unsigned long long)(sv >> 64);
        unsigned q = rbase + (unsigned)d1 * 32u;
        if (lo) atomicOr(&grid[q], lo);
        if (hi) atomicOr(&grid[q + 1], hi);
    }
}

// Reduce + zero + final sum in one kernel (last-block-done pattern).
// src^2: per halfword, key = b0+b1 = 2^L1 + 2^L2 - 2 is a perfect hash of the
// unordered level pair, and g(L1)+g(L2) is symmetric -> one LDS per 2 voxels.
// cross: per byte, key = thermo(Ls)+thermo(Lt); both-positive keys are even,
// single-sided keys odd (LUT=0) -> branchless vadd4 decode on rare taken path.
__global__ void reduce_kernel(float* __restrict__ out)
{
    __shared__ float s2tab[256];
    __shared__ float ctab[256];
    __shared__ float wsum[RTHREADS / 32];
    __shared__ double wsumd[RTHREADS / 32];
    __shared__ bool  isLast;

    const float KK = (float)((3.14159265358979323846 / 3.5) * (3.14159265358979323846 / 3.5));

    for (int i = threadIdx.x; i < 256; i += blockDim.x) { s2tab[i] = 0.0f; ctab[i] = 0.0f; }
    __syncthreads();
    if (threadIdx.x < 64) {
        int a = threadIdx.x >> 3, b = threadIdx.x & 7;
        int idx = (1 << a) + (1 << b) - 2;          // thermo(a)+thermo(b)
        float g1 = a ? expf(-2.0f * KK * (float)(7 - a)) : 0.0f;
        float g2 = b ? expf(-2.0f * KK * (float)(7 - b)) : 0.0f;
        s2tab[idx] = g1 + g2;                       // symmetric; dup writes benign
        ctab[idx]  = (a && b) ? expf(-KK * (float)(14 - a - b)) : 0.0f;
    }
    __syncthreads();

    float a0 = 0.0f, a1 = 0.0f, a2 = 0.0f, a3 = 0.0f;
    const uint4 z4 = make_uint4(0u, 0u, 0u, 0u);
    int base = (blockIdx.x * blockDim.x + threadIdx.x) * QPT;

    uint4 s[QPT], tq[QPT];
#pragma unroll
    for (int k = 0; k < QPT; k++) s[k]  = g_src[base + k];
#pragma unroll
    for (int k = 0; k < QPT; k++) tq[k] = g_tgt[base + k];

#pragma unroll
    for (int k = 0; k < QPT; k++) {
        unsigned sw[4] = { s[k].x,  s[k].y,  s[k].z,  s[k].w  };
        unsigned tw[4] = { tq[k].x, tq[k].y, tq[k].z, tq[k].w };
        unsigned sAny = sw[0] | sw[1] | sw[2] | sw[3];
        unsigned tAny = tw[0] | tw[1] | tw[2] | tw[3];
        if (sAny) {
            // src^2 term: batch keys, then lookups, into 4 independent accs
            unsigned kk[8];
#pragma unroll
            for (int l = 0; l < 4; l++) {
                kk[2 * l]     = __dp4a(sw[l], 0x00000101u, 0u);
                kk[2 * l + 1] = __dp4a(sw[l], 0x01010000u, 0u);
            }
            a0 += s2tab[kk[0]]; a1 += s2tab[kk[1]];
            a2 += s2tab[kk[2]]; a3 += s2tab[kk[3]];
            a0 += s2tab[kk[4]]; a1 += s2tab[kk[5]];
            a2 += s2tab[kk[6]]; a3 += s2tab[kk[7]];

            // cross term only when some voxel has both occupied (rare)
            unsigned uAny = (sw[0] & tw[0]) | (sw[1] & tw[1]) |
                            (sw[2] & tw[2]) | (sw[3] & tw[3]);
            if (uAny) {
#pragma unroll
                for (int l = 0; l < 4; l++) {
                    unsigned kw = __vaddus4(sw[l], tw[l]);
                    a0 -= ctab[kw & 255u];
                    a1 -= ctab[(kw >> 8)  & 255u];
                    a2 -= ctab[(kw >> 16) & 255u];
                    a3 -= ctab[kw >> 24];
                }
            }
            g_src[base + k] = z4;       // reset for next graph replay
        }
        if (tAny) g_tgt[base + k] = z4;
    }

    float acc = (a0 + a1) + (a2 + a3);
#pragma unroll
    for (int off = 16; off > 0; off >>= 1)
        acc += __shfl_down_sync(0xFFFFFFFFu, acc, off);
    int warp = threadIdx.x >> 5;
    if ((threadIdx.x & 31) == 0) wsum[warp] = acc;
    __syncthreads();
    if (threadIdx.x == 0) {
        float b = 0.0f;
#pragma unroll
        for (int wdx = 0; wdx < RTHREADS / 32; wdx++) b += wsum[wdx];
        g_part[blockIdx.x] = b;
        __threadfence();
        unsigned vdone = atomicAdd(&g_count, 1u);
        isLast = (vdone == (unsigned)gridDim.x - 1u);
        if (isLast) g_count = 0u;     // reset for next replay
    }
    __syncthreads();

    if (isLast) {
        double a = 0.0;
        for (int i = threadIdx.x; i < RBLOCKS; i += blockDim.x)
            a += (double)g_part[i];
#pragma unroll
        for (int off = 16; off > 0; off >>= 1)
            a += __shfl_down_sync(0xFFFFFFFFu, a, off);
        if ((threadIdx.x & 31) == 0) wsumd[warp] = a;
        __syncthreads();
        if (threadIdx.x == 0) {
            double tot = 0.0;
#pragma unroll
            for (int wdx = 0; wdx < RTHREADS / 32; wdx++) tot += wsumd[wdx];
            out[0] = (float)tot;
        }
    }
}

extern "C" void kernel_launch(void* const* d_in, const int* in_sizes, int n_in,
                              void* d_out, int out_size)
{
    const float* src = (const float*)d_in[0];
    const float* tgt = (const float*)d_in[1];
    const float* ox  = (const float*)d_in[2];
    const float* oy  = (const float*)d_in[3];
    const float* oz  = (const float*)d_in[4];
    const float* vx  = (const float*)d_in[5];
    int N = in_sizes[0] / 3;

    int total = 2 * N * 5;
    int blocks = (total + 255) / 256;
    splat_kernel<<<blocks, 256>>>(src, tgt, ox, oy, oz, vx, N);
    reduce_kernel<<<RBLOCKS, RTHREADS>>>((float*)d_out);
}